// round 17
// baseline (speedup 1.0000x reference)
#include <cuda_runtime.h>
#include <cstdint>
#include <math.h>

// ---------------------------------------------------------------------------
//   x: [4,16,64,64,64] f32    weights1/2: [2,4] f32    out: [4,32,32,32,32] f32
// <Z0> = v^T S v  ->  81 coeffs in double-angle basis (1, cos2a, sin2a),
// 2a = min(pi, pi*y). Two kernels:
//   build_W: 2x256, warp-shuffle sim -> g_W
//   main:    1152 x 256 threads:
//     [0,1024):    one (bc, j) slice; top thread bit = circuit set;
//                  each thread: 2 l-points of ONE set (8 sincos, 1 eval)
//     [1024,1152): zero-fill j>=16 half (64KB per block)
// ---------------------------------------------------------------------------

#define MAXOPS 64

struct Plan {
    int n;
    int type[MAXOPS];   // 0=RX, 1=RY, 2=RZ, 3=CNOT
    int a[MAXOPS];      // rot wire, or cnot control
    int b[MAXOPS];      // cnot target
    int widx[MAXOPS];   // weights flat index l*4+i
};

__device__ float g_W[2][81];

// ---------------------------------------------------------------------------
// Prelude (verified R9/R13): warp-shuffle circuit sim, bin, basis-change.
// ---------------------------------------------------------------------------
__global__ void build_W_kernel(const float* __restrict__ w1,
                               const float* __restrict__ w2,
                               Plan plan) {
    __shared__ float Ur[16][16], Ui[16][16];
    __shared__ float WA[81], WB[81];
    const float* w = (blockIdx.x == 0) ? w1 : w2;
    int t    = threadIdx.x;
    int col  = t >> 4;
    int amp  = t & 15;
    int lane = t & 31;

    float sr = (amp == col) ? 1.f : 0.f;
    float si = 0.f;

    for (int o = 0; o < plan.n; o++) {
        int ty = plan.type[o];
        if (ty == 3) {
            int bcb = 3 - plan.a[o], btb = 3 - plan.b[o];
            int src_amp  = amp ^ ((((amp >> bcb) & 1) ? 1 : 0) << btb);
            int src_lane = (lane & 16) | src_amp;
            sr = __shfl_sync(0xFFFFFFFFu, sr, src_lane);
            si = __shfl_sync(0xFFFFFFFFu, si, src_lane);
        } else {
            float th = w[plan.widx[o]];
            float c, s;
            __sincosf(0.5f * th, &s, &c);
            float a00r = c, a00i = 0.f, a01r = 0.f, a01i = 0.f;
            float a10r = 0.f, a10i = 0.f, a11r = c, a11i = 0.f;
            if (ty == 0)      { a01i = -s; a10i = -s; }      // RX
            else if (ty == 1) { a01r = -s; a10r =  s; }      // RY
            else              { a00i = -s; a11i =  s; }      // RZ
            int bitp = 3 - plan.a[o];
            int str  = 1 << bitp;
            float pr = __shfl_xor_sync(0xFFFFFFFFu, sr, str);
            float pi = __shfl_xor_sync(0xFFFFFFFFu, si, str);
            int bit = (amp >> bitp) & 1;
            float xr = bit ? pr : sr, xi = bit ? pi : si;
            float yr = bit ? sr : pr, yi = bit ? si : pi;
            float r0r = bit ? a10r : a00r, r0i = bit ? a10i : a00i;
            float r1r = bit ? a11r : a01r, r1i = bit ? a11i : a01i;
            sr = r0r * xr - r0i * xi + r1r * yr - r1i * yi;
            si = r0r * xi + r0i * xr + r1r * yi + r1i * yr;
        }
    }
    Ur[amp][col] = sr;
    Ui[amp][col] = si;
    if (t < 81) WA[t] = 0.f;
    __syncthreads();

    {
        int r = t >> 4, c = t & 15;
        float acc = 0.f;
        #pragma unroll
        for (int k = 0; k < 16; k++) {
            float z = (k & 8) ? -1.f : 1.f;
            acc += z * (Ur[k][r] * Ur[k][c] + Ui[k][r] * Ui[k][c]);
        }
        int m0 = ((r >> 3) & 1) + ((c >> 3) & 1);
        int m1 = ((r >> 2) & 1) + ((c >> 2) & 1);
        int m2 = ((r >> 1) & 1) + ((c >> 1) & 1);
        int m3 = (r & 1) + (c & 1);
        atomicAdd(&WA[((m0 * 3 + m1) * 3 + m2) * 3 + m3], acc);
    }

    #define XFORM(SRC, DST, S)                                            \
        __syncthreads();                                                  \
        if (t < 81) {                                                     \
            int n = (t / (S)) % 3;                                        \
            int base = t - n * (S);                                       \
            float i0 = SRC[base], i1 = SRC[base + (S)], i2 = SRC[base + 2 * (S)]; \
            DST[t] = (n == 0) ? 0.5f * (i0 + i2)                          \
                   : (n == 1) ? 0.5f * (i0 - i2) : 0.5f * i1;             \
        }
    XFORM(WA, WB, 27)
    XFORM(WB, WA, 9)
    XFORM(WA, WB, 3)
    XFORM(WB, WA, 1)
    #undef XFORM

    __syncthreads();
    if (t < 81) g_W[blockIdx.x][t] = WA[t];
}

// ---------------------------------------------------------------------------
// Main kernel: 1152 blocks x 256 threads.
// ---------------------------------------------------------------------------
__global__ void __launch_bounds__(256)
qconv_main_kernel(const float* __restrict__ x, float* __restrict__ out) {
    int t = threadIdx.x;

    if (blockIdx.x >= 1024) {
        // zero-fill: zi in [0,128) -> one (b, ch), full 64KB j>=16 half
        int zi = blockIdx.x - 1024;
        float4* dst = reinterpret_cast<float4*>(
            out + (size_t)(zi >> 5) * 1048576 + (size_t)(zi & 31) * 32768 + 16384);
        const float4 z4 = make_float4(0.f, 0.f, 0.f, 0.f);
        #pragma unroll
        for (int r = 0; r < 16; r++) dst[t + 256 * r] = z4;
        return;
    }

    // Padded W: rows of 12 floats (9 used), 16B-aligned rows -> LDS.128 reads
    __shared__ __align__(16) float Wsh[2][9][12];

    int bc  = blockIdx.x >> 4;    // b*16 + c
    int j   = blockIdx.x & 15;
    int set = t >> 7;             // circuit set 0/1
    int t7  = t & 127;
    int k   = t7 >> 3;            // 0..15
    int lq  = t7 & 7;             // points l = 2lq, 2lq+1

    const float* xb = x + (size_t)bc * 262144 + (size_t)(2 * j) * 4096
                        + (size_t)(2 * k) * 64 + 4 * lq;
    float4 v00 = *reinterpret_cast<const float4*>(xb);
    float4 v01 = *reinterpret_cast<const float4*>(xb + 64);
    float4 v10 = *reinterpret_cast<const float4*>(xb + 4096);
    float4 v11 = *reinterpret_cast<const float4*>(xb + 4096 + 64);

    // stage W (padded): 216 slots, 256 threads -> 1 round
    if (t < 216) {
        int s   = t / 108;
        int rem = t % 108;
        int a   = rem / 12;
        int col = rem % 12;
        Wsh[s][a][col] = (col < 9) ? g_W[s][a * 9 + col] : 0.f;
    }

    // Select this set's 4 corner angles per point (p = l parity).
    // set 0: q0=g(0,0,0) q1=g(1,1,0) q2=g(0,1,1) q3=g(1,0,1)
    //   -> v00.x/z, v11.x/z, v01.y/w, v10.y/w
    // set 1: q0=g(1,1,1) q1=g(0,0,1) q2=g(1,0,0) q3=g(0,1,0)
    //   -> v11.y/w, v00.y/w, v10.x/z, v01.x/z
    float q0p0 = set ? v11.y : v00.x,  q0p1 = set ? v11.w : v00.z;
    float q1p0 = set ? v00.y : v11.x,  q1p1 = set ? v00.w : v11.z;
    float q2p0 = set ? v10.x : v01.y,  q2p1 = set ? v10.z : v01.w;
    float q3p0 = set ? v01.x : v10.y,  q3p1 = set ? v01.z : v10.w;

    const float PI_F = 3.14159265358979323846f;
    float Ca0, Sa0, Ca1, Sa1, Cb0, Sb0, Cb1, Sb1;
    float Cc0, Sc0, Cc1, Sc1, Cd0, Sd0, Cd1, Sd1;
    __sincosf(fminf(PI_F, PI_F * q0p0), &Sa0, &Ca0);
    __sincosf(fminf(PI_F, PI_F * q0p1), &Sa1, &Ca1);
    __sincosf(fminf(PI_F, PI_F * q1p0), &Sb0, &Cb0);
    __sincosf(fminf(PI_F, PI_F * q1p1), &Sb1, &Cb1);
    __sincosf(fminf(PI_F, PI_F * q2p0), &Sc0, &Cc0);
    __sincosf(fminf(PI_F, PI_F * q2p1), &Sc1, &Cc1);
    __sincosf(fminf(PI_F, PI_F * q3p0), &Sd0, &Cd0);
    __sincosf(fminf(PI_F, PI_F * q3p1), &Sd1, &Cd1);

    __syncthreads();   // Wsh ready

    // monomials: rows (q0,q1), cols (q2,q3); per point
    float M01[2][9] = {
        { 1.f, Cb0, Sb0, Ca0, Ca0 * Cb0, Ca0 * Sb0, Sa0, Sa0 * Cb0, Sa0 * Sb0 },
        { 1.f, Cb1, Sb1, Ca1, Ca1 * Cb1, Ca1 * Sb1, Sa1, Sa1 * Cb1, Sa1 * Sb1 }
    };
    float M23[2][9] = {
        { 1.f, Cd0, Sd0, Cc0, Cc0 * Cd0, Cc0 * Sd0, Sc0, Sc0 * Cd0, Sc0 * Sd0 },
        { 1.f, Cd1, Sd1, Cc1, Cc1 * Cd1, Cc1 * Sd1, Sc1, Sc1 * Cd1, Sc1 * Sd1 }
    };

    float e0 = 0.f, e1 = 0.f;
    #pragma unroll
    for (int a = 0; a < 9; a++) {
        // 9-float W row via 2x LDS.128 + 1x LDS.32 (rows 48B, 16B aligned)
        float4 wA = *reinterpret_cast<const float4*>(&Wsh[set][a][0]);
        float4 wB = *reinterpret_cast<const float4*>(&Wsh[set][a][4]);
        float  w8 = Wsh[set][a][8];
        float t0, t1;
        t0 = wA.x * M23[0][0];                 t1 = wA.x * M23[1][0];
        t0 = fmaf(wA.y, M23[0][1], t0);        t1 = fmaf(wA.y, M23[1][1], t1);
        t0 = fmaf(wA.z, M23[0][2], t0);        t1 = fmaf(wA.z, M23[1][2], t1);
        t0 = fmaf(wA.w, M23[0][3], t0);        t1 = fmaf(wA.w, M23[1][3], t1);
        t0 = fmaf(wB.x, M23[0][4], t0);        t1 = fmaf(wB.x, M23[1][4], t1);
        t0 = fmaf(wB.y, M23[0][5], t0);        t1 = fmaf(wB.y, M23[1][5], t1);
        t0 = fmaf(wB.z, M23[0][6], t0);        t1 = fmaf(wB.z, M23[1][6], t1);
        t0 = fmaf(wB.w, M23[0][7], t0);        t1 = fmaf(wB.w, M23[1][7], t1);
        t0 = fmaf(w8,   M23[0][8], t0);        t1 = fmaf(w8,   M23[1][8], t1);
        e0 = fmaf(M01[0][a], t0, e0);
        e1 = fmaf(M01[1][a], t1, e1);
    }

    // ---- DIRECT epilogue (own set's slice only) ----
    int b = bc >> 4, c = bc & 15;
    float* base = out + (size_t)b * 1048576 + (size_t)(c + 16 * set) * 32768
                      + (size_t)j * 1024;
    *reinterpret_cast<float2*>(base + k * 32 + 2 * lq)      = make_float2(e0, e1);
    *reinterpret_cast<float2*>(base + k * 32 + 16 + 2 * lq) = make_float2(0.f, 0.f);
    int zrow = 16 + (t7 >> 3);
    int zcol = 4 * (t7 & 7);
    *reinterpret_cast<float4*>(base + zrow * 32 + zcol) =
        make_float4(0.f, 0.f, 0.f, 0.f);
}

// ---------------------------------------------------------------------------
// Host: exact numpy default_rng(1234) plan generation (verified R3).
// ---------------------------------------------------------------------------
typedef unsigned __int128 u128;

struct NpRng {
    u128 state, inc;
    bool has32;
    uint32_t buf32;

    static u128 mult() {
        return ((u128)2549297995355413924ULL << 64) | 4865540595714422341ULL;
    }
    uint64_t next64() {
        state = state * mult() + inc;
        uint64_t hi = (uint64_t)(state >> 64);
        uint64_t lo = (uint64_t)state;
        unsigned rot = (unsigned)(state >> 122);
        uint64_t v = hi ^ lo;
        return (v >> rot) | (v << ((64u - rot) & 63u));
    }
    uint32_t next32() {
        if (has32) { has32 = false; return buf32; }
        uint64_t n = next64();
        has32 = true;
        buf32 = (uint32_t)(n >> 32);
        return (uint32_t)n;
    }
    double nextDouble() {
        return (double)(next64() >> 11) * (1.0 / 9007199254740992.0);
    }
    uint32_t lemire32(uint32_t rng) {
        uint32_t rng_excl = rng + 1u;
        uint64_t m = (uint64_t)next32() * (uint64_t)rng_excl;
        uint32_t leftover = (uint32_t)m;
        if (leftover < rng_excl) {
            uint32_t threshold = (uint32_t)((0xFFFFFFFFu - rng) % rng_excl);
            while (leftover < threshold) {
                m = (uint64_t)next32() * (uint64_t)rng_excl;
                leftover = (uint32_t)m;
            }
        }
        return (uint32_t)(m >> 32);
    }
};

static Plan make_plan_host() {
    const uint32_t INIT_A = 0x43b0d7e5u, MULT_A = 0x931e8875u;
    const uint32_t INIT_B = 0x8b51f9ddu, MULT_B = 0x58f38dedu;
    const uint32_t MIX_L  = 0xca01f9ddu, MIX_R  = 0x4973f715u;

    uint32_t pool[4];
    uint32_t hc = INIT_A;
    auto hashmix = [&](uint32_t v) -> uint32_t {
        v ^= hc; hc *= MULT_A; v *= hc; v ^= v >> 16; return v;
    };
    auto mixf = [&](uint32_t x, uint32_t y) -> uint32_t {
        uint32_t r = x * MIX_L - y * MIX_R; r ^= r >> 16; return r;
    };
    pool[0] = hashmix(1234u);
    pool[1] = hashmix(0u);
    pool[2] = hashmix(0u);
    pool[3] = hashmix(0u);
    for (int s = 0; s < 4; s++)
        for (int d = 0; d < 4; d++)
            if (s != d) pool[d] = mixf(pool[d], hashmix(pool[s]));

    uint32_t hb = INIT_B;
    uint32_t st32[8];
    for (int i = 0; i < 8; i++) {
        uint32_t dv = pool[i & 3];
        dv ^= hb; hb *= MULT_B; dv *= hb; dv ^= dv >> 16;
        st32[i] = dv;
    }
    uint64_t s64[4];
    for (int i = 0; i < 4; i++)
        s64[i] = (uint64_t)st32[2 * i] | ((uint64_t)st32[2 * i + 1] << 32);

    NpRng rng;
    u128 initstate = ((u128)s64[0] << 64) | s64[1];
    u128 initseq   = ((u128)s64[2] << 64) | s64[3];
    rng.inc   = (initseq << 1) | 1;
    rng.state = 0;
    rng.state = rng.state * NpRng::mult() + rng.inc;
    rng.state += initstate;
    rng.state = rng.state * NpRng::mult() + rng.inc;
    rng.has32 = false;
    rng.buf32 = 0;

    Plan plan;
    plan.n = 0;
    for (int l = 0; l < 2; l++) {
        int i = 0;
        while (i < 4 && plan.n < MAXOPS) {
            if (rng.nextDouble() > 0.3) {
                int g = (int)rng.lemire32(2);
                int w = (int)rng.lemire32(3);
                plan.type[plan.n] = g;
                plan.a[plan.n]    = w;
                plan.b[plan.n]    = 0;
                plan.widx[plan.n] = l * 4 + i;
                plan.n++;
                i++;
            } else {
                uint64_t hash_set[4] = { ~0ULL, ~0ULL, ~0ULL, ~0ULL };
                int64_t idx[2];
                for (int jf = 2; jf <= 3; jf++) {
                    uint64_t val = (uint64_t)rng.lemire32((uint32_t)jf);
                    uint64_t loc = val & 3;
                    while (hash_set[loc] != ~0ULL && hash_set[loc] != val)
                        loc = (loc + 1) & 3;
                    if (hash_set[loc] == ~0ULL) {
                        hash_set[loc] = val;
                        idx[jf - 2] = (int64_t)val;
                    } else {
                        loc = (uint64_t)jf & 3;
                        while (hash_set[loc] != ~0ULL) loc = (loc + 1) & 3;
                        hash_set[loc] = (uint64_t)jf;
                        idx[jf - 2] = jf;
                    }
                }
                uint32_t sh = rng.lemire32(1u);   // Lemire-32 (top bit)
                int64_t tmp = idx[1]; idx[1] = idx[sh]; idx[sh] = tmp;

                plan.type[plan.n] = 3;
                plan.a[plan.n]    = (int)idx[0];
                plan.b[plan.n]    = (int)idx[1];
                plan.widx[plan.n] = 0;
                plan.n++;
            }
        }
    }
    return plan;
}

// ---------------------------------------------------------------------------
extern "C" void kernel_launch(void* const* d_in, const int* in_sizes, int n_in,
                              void* d_out, int out_size) {
    const float* x  = (const float*)d_in[0];
    const float* w1 = (const float*)d_in[1];
    const float* w2 = (const float*)d_in[2];
    float* out = (float*)d_out;

    Plan plan = make_plan_host();

    build_W_kernel<<<2, 256>>>(w1, w2, plan);
    qconv_main_kernel<<<1152, 256>>>(x, out);
}